// round 9
// baseline (speedup 1.0000x reference)
#include <cuda_runtime.h>
#include <cuda_bf16.h>
#include <cstdint>

// BatchDepthwiseCrossCorrelation via warp-level HMMA (mma.sync bf16, 3-pass hi/lo split)
// with a register sliding window over y (8 pre-split rows live per thread).
//   x:         [8, 256, 64, 64]  f32
//   templates: [8, 8, 256, 7, 7] f32
//   out:       [8, 8, 256, 64, 64] f32
// Per channel c: out[p, nt] = sum_tap patch[p, tap] * t[nt, tap]
// GEMM: M = 16 pixels, N = 8 (nt), K = 64 (taps ky*8+kx; kx=7 & ky=7 rows zero in B)

#define BSNC   2048
#define HI     64
#define WI     64
#define PLANE  (HI*WI)
#define PAD    3
#define NT     8
#define QROWS  16                 // output rows per CTA (quarter plane)
#define SROWS  23                 // padded input rows staged (ty+ky max = 15+7 = 22)
#define SPW    72                 // plane row pitch in u32 words
#define KDIM   64
#define NTHREADS 128

__device__ __forceinline__ uint32_t split_pack(float v) {
    __nv_bfloat16 h = __float2bfloat16(v);
    float hf = __bfloat162float(h);
    __nv_bfloat16 l = __float2bfloat16(v - hf);
    return ((uint32_t)__bfloat16_as_ushort(h) << 16) | (uint32_t)__bfloat16_as_ushort(l);
}

__device__ __forceinline__ void mma_bf16(float& d0, float& d1, float& d2, float& d3,
                                         uint32_t a0, uint32_t a1, uint32_t a2, uint32_t a3,
                                         uint32_t b0, uint32_t b1) {
    asm volatile(
        "mma.sync.aligned.m16n8k16.row.col.f32.bf16.bf16.f32 "
        "{%0,%1,%2,%3}, {%4,%5,%6,%7}, {%8,%9}, {%0,%1,%2,%3};"
        : "+f"(d0), "+f"(d1), "+f"(d2), "+f"(d3)
        : "r"(a0), "r"(a1), "r"(a2), "r"(a3), "r"(b0), "r"(b1));
}

__global__ __launch_bounds__(NTHREADS, 7)
void dwxcorr_hmma_kernel(const float* __restrict__ x,
                         const float* __restrict__ tm,
                         float* __restrict__ out)
{
    __shared__ uint32_t s_plane[SROWS * SPW];           // packed {bf16 hi | bf16 lo}
    __shared__ __align__(16) uint32_t s_tmpl[NT][KDIM]; // packed templates, tap = ky*8+kx

    const int c   = blockIdx.x >> 2;            // fused (b, ch) channel
    const int y0  = (blockIdx.x & 3) * QROWS;   // top output row of this quarter
    const int tid = threadIdx.x;
    const int wid = tid >> 5;
    const int lane = tid & 31;
    const int q = lane & 3;                     // k-pair / nt-pair index
    const int r = lane >> 2;                    // row-in-group index

    // ---- Prologue: zero-fill plane + template buffers ----
    for (int i = tid; i < SROWS * SPW; i += NTHREADS) s_plane[i] = 0u;
    for (int i = tid; i < NT * KDIM; i += NTHREADS) ((uint32_t*)s_tmpl)[i] = 0u;
    __syncthreads();

    // Interior copy: padded rows a (plane row gy = y0 + a - 3), real taps use a <= 21.
    {
        const int a0 = (y0 == 0) ? PAD : 0;
        int a1 = 66 - y0; if (a1 > 21) a1 = 21;
        const int nrows = a1 - a0 + 1;
        const float* src = x + (size_t)c * PLANE + (size_t)(y0 + a0 - PAD) * WI;
        for (int i = tid; i < nrows * WI; i += NTHREADS) {
            int rr = i >> 6;
            int cc = i & 63;
            s_plane[(a0 + rr) * SPW + cc + PAD] = split_pack(src[i]);
        }
    }
    // Templates: scatter taps into [nt][ky*8+kx] (kx=7, ky=7 stay zero).
    for (int i = tid; i < NT * 49; i += NTHREADS) {
        int nt = i / 49, tap = i - nt * 49;
        int ky = tap / 7, kx = tap - ky * 7;
        s_tmpl[nt][ky * 8 + kx] = split_pack(tm[((size_t)nt * BSNC + c) * 49 + tap]);
    }
    __syncthreads();

    // ---- B fragments (templates) into registers: loop-invariant per channel ----
    uint32_t bh[8], bl[8];
    {
        const uint32_t* tb = &s_tmpl[r][2 * q];
        #pragma unroll
        for (int ch = 0; ch < 4; ch++) {
            uint2 w = *(const uint2*)(tb + ch * 16);
            bh[2 * ch]     = __byte_perm(w.x, w.y, 0x7632);
            bl[2 * ch]     = __byte_perm(w.x, w.y, 0x5410);
            uint2 v = *(const uint2*)(tb + ch * 16 + 8);
            bh[2 * ch + 1] = __byte_perm(v.x, v.y, 0x7632);
            bl[2 * ch + 1] = __byte_perm(v.x, v.y, 0x5410);
        }
    }

    const size_t planeN = (size_t)BSNC * PLANE;
    const int x0 = wid << 4;                    // each warp owns one 16-wide x strip
    const uint32_t xbase = (uint32_t)(x0 + r + 2 * q);
    float* obase = out + (size_t)c * PLANE + (size_t)y0 * WI
                 + (size_t)(x0 + r) + (size_t)(2 * q) * planeN;

    // ---- Sliding window: 8 pre-split rows live in registers, rotating slots ----
    uint32_t ah[8], al[8], ah8[8], al8[8];

#define LOAD_ROW(a, s) do {                                            \
        const uint32_t* _p = &s_plane[(a) * SPW + xbase];              \
        uint32_t _w0 = _p[0], _w1 = _p[1], _w8 = _p[8], _w9 = _p[9];   \
        ah[s]  = __byte_perm(_w0, _w1, 0x7632);                        \
        al[s]  = __byte_perm(_w0, _w1, 0x5410);                        \
        ah8[s] = __byte_perm(_w8, _w9, 0x7632);                        \
        al8[s] = __byte_perm(_w8, _w9, 0x5410);                        \
    } while (0)

    #pragma unroll
    for (int a = 0; a < 8; a++) LOAD_ROW(a, a);

    #pragma unroll
    for (int ty = 0; ty < QROWS; ty++) {
        float d0 = 0.f, d1 = 0.f, d2 = 0.f, d3 = 0.f;

        #pragma unroll
        for (int ch = 0; ch < 4; ch++) {
            const int s0 = (ty + 2 * ch)     & 7;   // ky = 2ch row slot
            const int s1 = (ty + 2 * ch + 1) & 7;   // ky = 2ch+1 row slot
            mma_bf16(d0, d1, d2, d3, ah[s0], ah8[s0], ah[s1], ah8[s1], bh[2*ch], bh[2*ch+1]);
            mma_bf16(d0, d1, d2, d3, ah[s0], ah8[s0], ah[s1], ah8[s1], bl[2*ch], bl[2*ch+1]);
            mma_bf16(d0, d1, d2, d3, al[s0], al8[s0], al[s1], al8[s1], bh[2*ch], bh[2*ch+1]);
        }

        float* ob = obase + (size_t)ty * WI;
        ob[0]          = d0;    // (pixel x0+r,   nt 2q)
        ob[planeN]     = d1;    // (pixel x0+r,   nt 2q+1)
        ob[8]          = d2;    // (pixel x0+r+8, nt 2q)
        ob[planeN + 8] = d3;    // (pixel x0+r+8, nt 2q+1)

        if (ty < QROWS - 1) LOAD_ROW(ty + 8, (ty + 8) & 7);
    }
#undef LOAD_ROW
}

extern "C" void kernel_launch(void* const* d_in, const int* in_sizes, int n_in,
                              void* d_out, int out_size)
{
    const float* x  = (const float*)d_in[0];
    const float* tm = (const float*)d_in[1];
    float* out      = (float*)d_out;
    dwxcorr_hmma_kernel<<<BSNC * 4, NTHREADS>>>(x, tm, out);
}

// round 11
// speedup vs baseline: 1.1606x; 1.1606x over previous
#include <cuda_runtime.h>
#include <cuda_bf16.h>
#include <cstdint>

// BatchDepthwiseCrossCorrelation via warp HMMA (bf16 3-pass hi/lo split),
// M = 2 y-rows x 8 x-pixels, register window of pre-split pair-fragments.
//   x:         [8, 256, 64, 64]  f32
//   templates: [8, 8, 256, 7, 7] f32
//   out:       [8, 8, 256, 64, 64] f32
// Per channel c: out[p, nt] = sum_tap patch[p, tap] * t[nt, tap]
// MMA rows 0-7 = pixels (ty, x0+r), rows 8-15 = (ty+1, x0+r); cols = nt; K = 64.

#define BSNC   2048
#define HI     64
#define WI     64
#define PLANE  (HI*WI)
#define PAD    3
#define NT     8
#define QROWS  16                 // output rows per CTA (quarter plane)
#define SROWS  23                 // padded plane rows staged
#define SPW    72                 // pair-plane row pitch (uint2 words)
#define KDIM   64
#define NTHREADS 128

__device__ __forceinline__ void mma_bf16(float& d0, float& d1, float& d2, float& d3,
                                         uint32_t a0, uint32_t a1, uint32_t a2, uint32_t a3,
                                         uint32_t b0, uint32_t b1) {
    asm volatile(
        "mma.sync.aligned.m16n8k16.row.col.f32.bf16.bf16.f32 "
        "{%0,%1,%2,%3}, {%4,%5,%6,%7}, {%8,%9}, {%0,%1,%2,%3};"
        : "+f"(d0), "+f"(d1), "+f"(d2), "+f"(d3)
        : "r"(a0), "r"(a1), "r"(a2), "r"(a3), "r"(b0), "r"(b1));
}

__device__ __forceinline__ uint32_t split_pack(float v) {
    __nv_bfloat16 h = __float2bfloat16(v);
    __nv_bfloat16 l = __float2bfloat16(v - __bfloat162float(h));
    return ((uint32_t)__bfloat16_as_ushort(h) << 16) | (uint32_t)__bfloat16_as_ushort(l);
}
// pair fragment words: hi = {h(x) lo16, h(x+1) hi16}, lo likewise (mma a-frag order)
__device__ __forceinline__ uint2 pair_split(float v0, float v1) {
    __nv_bfloat16 h0 = __float2bfloat16(v0);
    __nv_bfloat16 l0 = __float2bfloat16(v0 - __bfloat162float(h0));
    __nv_bfloat16 h1 = __float2bfloat16(v1);
    __nv_bfloat16 l1 = __float2bfloat16(v1 - __bfloat162float(h1));
    uint2 w;
    w.x = (uint32_t)__bfloat16_as_ushort(h0) | ((uint32_t)__bfloat16_as_ushort(h1) << 16);
    w.y = (uint32_t)__bfloat16_as_ushort(l0) | ((uint32_t)__bfloat16_as_ushort(l1) << 16);
    return w;
}

__global__ __launch_bounds__(NTHREADS, 8)
void dwxcorr_hmma_kernel(const float* __restrict__ x,
                         const float* __restrict__ tm,
                         float* __restrict__ out)
{
    __shared__ uint2 s_pair[SROWS][SPW];                // pre-split pair fragments
    __shared__ __align__(16) uint32_t s_tmpl[NT][KDIM]; // packed templates {hi|lo}, tap = ky*8+kx

    const int c   = blockIdx.x >> 2;            // fused (b, ch) channel
    const int y0  = (blockIdx.x & 3) * QROWS;   // top output row of this quarter
    const int tid = threadIdx.x;
    const int wid = tid >> 5;
    const int lane = tid & 31;
    const int q = lane & 3;                     // k-pair / nt-pair index
    const int r = lane >> 2;                    // row-in-group index

    // ---- Prologue: zero-fill pair plane + template buffer ----
    for (int i = tid; i < SROWS * SPW; i += NTHREADS) ((uint2*)s_pair)[i] = make_uint2(0u, 0u);
    for (int i = tid; i < NT * KDIM; i += NTHREADS) ((uint32_t*)s_tmpl)[i] = 0u;
    __syncthreads();

    // Fill valid rows: padded row a holds plane row gy = y0 + a - 3.
    {
        const int a0 = (y0 == 0) ? PAD : 0;
        int a1 = 66 - y0; if (a1 > SROWS - 1) a1 = SROWS - 1;
        const int nrows = a1 - a0 + 1;
        const float* xc = x + (size_t)c * PLANE;
        for (int i = tid; i < nrows * 71; i += NTHREADS) {
            int rr = i / 71;
            int cc = i - rr * 71;
            int gy = y0 + (a0 + rr) - PAD;
            const float* row = xc + (size_t)gy * WI;
            int gx0 = cc - PAD, gx1 = cc - PAD + 1;
            float v0 = (gx0 >= 0 && gx0 < WI) ? row[gx0] : 0.0f;
            float v1 = (gx1 >= 0 && gx1 < WI) ? row[gx1] : 0.0f;
            s_pair[a0 + rr][cc] = pair_split(v0, v1);
        }
    }
    // Templates: scatter taps into [nt][ky*8+kx] (kx=7, ky=7 stay zero).
    for (int i = tid; i < NT * 49; i += NTHREADS) {
        int nt = i / 49, tap = i - nt * 49;
        int ky = tap / 7, kx = tap - ky * 7;
        s_tmpl[nt][ky * 8 + kx] = split_pack(tm[((size_t)nt * BSNC + c) * 49 + tap]);
    }
    __syncthreads();

    // ---- B fragments (templates) into registers: loop-invariant per channel ----
    uint32_t bh[8], bl[8];
    {
        const uint32_t* tb = &s_tmpl[r][2 * q];
        #pragma unroll
        for (int ch = 0; ch < 4; ch++) {
            uint2 w = *(const uint2*)(tb + ch * 16);
            bh[2 * ch]     = __byte_perm(w.x, w.y, 0x7632);
            bl[2 * ch]     = __byte_perm(w.x, w.y, 0x5410);
            uint2 v = *(const uint2*)(tb + ch * 16 + 8);
            bh[2 * ch + 1] = __byte_perm(v.x, v.y, 0x7632);
            bl[2 * ch + 1] = __byte_perm(v.x, v.y, 0x5410);
        }
    }

    const size_t planeN = (size_t)BSNC * PLANE;

    // ---- Mainloop: 2 x-strips per warp, 8 y-pair tiles per strip ----
    #pragma unroll
    for (int sidx = 0; sidx < 2; sidx++) {
        const int x0 = (wid + 4 * sidx) * 8;
        const int xf = x0 + r + 2 * q;          // fixed fragment x for this thread
        float* obase = out + (size_t)c * PLANE + (size_t)y0 * WI
                     + (size_t)(x0 + r) + (size_t)(2 * q) * planeN;

        uint2 W[SROWS];                         // constant-indexed; live range <= 11

        #pragma unroll
        for (int a = 0; a < 9; a++) W[a] = s_pair[a][xf];

        #pragma unroll
        for (int typ = 0; typ < 8; typ++) {
            const int ty = 2 * typ;
            float d0 = 0.f, d1 = 0.f, d2 = 0.f, d3 = 0.f;

            #pragma unroll
            for (int ch = 0; ch < 4; ch++) {
                const int s = ty + 2 * ch;
                // a0=(y,ky) a1=(y+1,ky) a2=(y,ky+1)=a1's row  a3=(y+1,ky+1)
                mma_bf16(d0, d1, d2, d3,
                         W[s].x, W[s + 1].x, W[s + 1].x, W[s + 2].x,
                         bh[2 * ch], bh[2 * ch + 1]);
                mma_bf16(d0, d1, d2, d3,
                         W[s].x, W[s + 1].x, W[s + 1].x, W[s + 2].x,
                         bl[2 * ch], bl[2 * ch + 1]);
                mma_bf16(d0, d1, d2, d3,
                         W[s].y, W[s + 1].y, W[s + 1].y, W[s + 2].y,
                         bh[2 * ch], bh[2 * ch + 1]);
            }

            float* ob = obase + (size_t)ty * WI;
            ob[0]               = d0;   // (pixel ty,   nt 2q)
            ob[planeN]          = d1;   // (pixel ty,   nt 2q+1)
            ob[WI]              = d2;   // (pixel ty+1, nt 2q)
            ob[planeN + WI]     = d3;   // (pixel ty+1, nt 2q+1)

            if (typ < 7) {
                W[ty + 9]  = s_pair[ty + 9][xf];
                W[ty + 10] = s_pair[ty + 10][xf];
            }
        }
    }
}

extern "C" void kernel_launch(void* const* d_in, const int* in_sizes, int n_in,
                              void* d_out, int out_size)
{
    const float* x  = (const float*)d_in[0];
    const float* tm = (const float*)d_in[1];
    float* out      = (float*)d_out;
    dwxcorr_hmma_kernel<<<BSNC * 4, NTHREADS>>>(x, tm, out);
}